// round 10
// baseline (speedup 1.0000x reference)
#include <cuda_runtime.h>
#include <cstdint>

// ---------------- problem constants ----------------
#define B_    32
#define E_    256
#define N_    512
#define HID   64
#define H_    4
#define F_    64
#define C_    256
#define S_    255
#define BH_   (B_*H_)
#define NE_ELEMS (B_*N_*C_)
#define ADJ_ELEMS (B_*14*N_*N_)
#define MROWS ((B_*N_)/128)
#define FILL_TOTAL (32*14*32)
#define FILL_A (FILL_TOTAL/2)
#define FILL_B (FILL_TOTAL - FILL_A)

#define PA 20
#define PW 136
#define FQ 8          // channels per fusedscan block
#define PV 9          // V pitch (coprime to 32 => conflict-free row access)

// ---------------- scratch ----------------
__device__ float  g_x   [B_*N_*HID];
__device__ float  g_h   [B_*N_*C_];
__device__ float  g_o1  [B_*N_*C_];
__device__ int    g_rank[BH_*N_];    // by original index
__device__ float  g_e1  [BH_*N_];    // exp(b_i - mb), by original index
__device__ float  g_e2  [BH_*N_];    // exp(0.2(b_i - mb)), by original index
__device__ float4 g_pkc [BH_*N_];    // (c1,c2,ns,t) by original index

__device__ __forceinline__ float to_tf32(float x) {
    float r; asm("cvt.rna.tf32.f32 %0, %1;" : "=f"(r) : "f"(x)); return r;
}

__device__ __forceinline__ void mma_tf32(float4& d,
                                         uint32_t a0, uint32_t a1, uint32_t a2, uint32_t a3,
                                         uint32_t b0, uint32_t b1) {
    asm("mma.sync.aligned.m16n8k8.row.col.f32.tf32.tf32.f32 "
        "{%0,%1,%2,%3},{%4,%5,%6,%7},{%8,%9},{%0,%1,%2,%3};"
        : "+f"(d.x), "+f"(d.y), "+f"(d.z), "+f"(d.w)
        : "r"(a0), "r"(a1), "r"(a2), "r"(a3), "r"(b0), "r"(b1));
}

// ============================================================
// Adjacency fill (one 256-thread block's share).
// ============================================================
__device__ __forceinline__ void fill_block(int fid, int t, float* __restrict__ out) {
    int x = fid & 31;
    int rest = fid >> 5;
    int r = rest % 14;
    int b = rest / 14;
    int n  = x * 16 + (t >> 4);
    int m0 = (t & 15) * 32;
    float* p = out + ((((long long)b * 14 + r) * N_ + n) << 9) + m0;
    float4* p4 = reinterpret_cast<float4*>(p);

    if (r < 13) {
        float4 z = make_float4(0.f, 0.f, 0.f, 0.f);
        #pragma unroll
        for (int q = 0; q < 8; q++) __stcs(p4 + q, z);
        if (r >= 11) {
            int cu = n + 2;
            if (cu < N_ && cu >= m0 && cu < m0 + 32) {
                int rel = ((n & 3) == 0 || (n & 3) == 3) ? 11 : 12;
                if (rel == r) p[cu - m0] = 1.f;
            }
            int cd = n - 2;
            if (cd >= 0 && cd >= m0 && cd < m0 + 32) {
                int pp = n - 2;
                int rel = ((pp & 3) == 0 || (pp & 3) == 3) ? 11 : 12;
                if (rel == r) p[cd - m0] = 1.f;
            }
        }
        return;
    }
    if (n + 3 < m0 || n - 3 >= m0 + 32) {
        float4 o1 = make_float4(1.f, 1.f, 1.f, 1.f);
        #pragma unroll
        for (int q = 0; q < 8; q++) __stcs(p4 + q, o1);
        return;
    }
    int sp1 = -1, sp2 = -1;
    int nm = n & 3;
    if (nm == 0) {
        if (n <= 508) sp1 = n + 3;
        if (n >= 4)   sp2 = n - 1;
    } else if (nm == 3) {
        if (n <= 507) sp1 = n + 1;
        sp2 = n - 3;
    }
    float vals[32];
    #pragma unroll
    for (int q = 0; q < 32; q++) {
        int m = m0 + q;
        bool zero = (m == n) | (m == n - 2) | (m == n + 2) | (m == sp1) | (m == sp2);
        vals[q] = zero ? 0.f : 1.f;
    }
    #pragma unroll
    for (int q = 0; q < 8; q++)
        __stcs(p4 + q, make_float4(vals[4*q], vals[4*q+1], vals[4*q+2], vals[4*q+3]));
}

__global__ void scatter_kernel(const int* __restrict__ shot, float* __restrict__ out) {
    int idx = blockIdx.x * 256 + threadIdx.x;
    if (idx >= B_ * S_) return;
    int b = idx / S_, s = idx % S_;
    int r = shot[idx];
    int i, j;
    if ((s & 1) == 0) { i = 2 * s;     j = 2 * s + 3; }
    else              { i = 2 * s + 1; j = 2 * s + 2; }
    long long base = ((long long)b * 14 + r) * (N_ * N_);
    out[base + (long long)i * N_ + j] = 1.f;
    out[base + (long long)j * N_ + i] = 1.f;
}

// ============================================================
// Kernel 2: node features.
// ============================================================
__global__ void feat_kernel(const int* __restrict__ player,
                            const float* __restrict__ Ax, const float* __restrict__ Ay,
                            const float* __restrict__ Bx, const float* __restrict__ By,
                            const float* __restrict__ emb,
                            const float* __restrict__ Wc, const float* __restrict__ bc,
                            const float* __restrict__ Wm, const float* __restrict__ bm,
                            float* __restrict__ x) {
    __shared__ float feat[32][64];
    __shared__ float wms[64 * 64];
    int blk = blockIdx.x;
    int b = blk >> 4;
    int n0 = (blk & 15) * 32;
    int tid = threadIdx.x;

    #pragma unroll
    for (int it = 0; it < 16; it++) wms[it * 256 + tid] = Wm[it * 256 + tid];

    #pragma unroll
    for (int it = 0; it < 8; it++) {
        int o = it * 256 + tid;
        int nl = o >> 6, c = o & 63;
        int n = n0 + nl;
        int e = n >> 1;
        float val;
        if (c < 32) {
            float cx, cy;
            if ((n & 1) == 0) { cx = Ax[b * E_ + e]; cy = Ay[b * E_ + e]; }
            else              { cx = Bx[b * E_ + e]; cy = By[b * E_ + e]; }
            val = fmaxf(cx * Wc[c] + cy * Wc[32 + c] + bc[c], 0.f);
        } else {
            int pid = player[b * 2 + (n & 1)];
            val = emb[pid * 32 + (c - 32)];
        }
        feat[nl][c] = val;
    }
    __syncthreads();

    #pragma unroll
    for (int it = 0; it < 8; it++) {
        int o = it * 256 + tid;
        int nl = o >> 6, k = o & 63;
        float acc = bm[k];
        #pragma unroll
        for (int c = 0; c < 64; c++) acc += feat[nl][c] * wms[c * 64 + k];
        x[(b * N_ + n0 + nl) * HID + k] = acc;
    }
}

// ============================================================
// Kernel 3: hybrid tf32-MMA SGEMM + adjacency fill.
// ============================================================
template<int KIN>
__global__ void __launch_bounds__(256, 2)
gemm_fill_kernel(const float* __restrict__ A, const float* __restrict__ W,
                 float* __restrict__ C, float* __restrict__ adj, int fill_base) {
    if (blockIdx.y >= MROWS) {
        int fid = fill_base + (blockIdx.y - MROWS) * 2 + blockIdx.x;
        fill_block(fid, threadIdx.x, adj);
        return;
    }
    __shared__ float As[2][128 * PA];
    __shared__ float Ws[2][16 * PW];
    const int Kout = C_;
    int tid = threadIdx.x;
    int mt = blockIdx.y * 128, nt = blockIdx.x * 128;
    int wid = tid >> 5, lane = tid & 31;
    int g = lane >> 2, t4 = lane & 3;
    int m0w = (wid >> 1) * 32;
    int n0w = (wid & 1) * 64;

    int ar = tid >> 1;
    int ak = (tid & 1) * 8;
    int wr = tid >> 4;
    int wc = (tid & 15) * 8;

    float4 acc[2][8];
    #pragma unroll
    for (int mi = 0; mi < 2; mi++)
        #pragma unroll
        for (int ni = 0; ni < 8; ni++) acc[mi][ni] = make_float4(0.f, 0.f, 0.f, 0.f);

    const float* Arow = &A[(long long)(mt + ar) * KIN];

    {
        float4 a0 = *reinterpret_cast<const float4*>(&Arow[ak]);
        float4 a1 = *reinterpret_cast<const float4*>(&Arow[ak + 4]);
        float* d = &As[0][ar * PA + ak];
        d[0] = to_tf32(a0.x); d[1] = to_tf32(a0.y); d[2] = to_tf32(a0.z); d[3] = to_tf32(a0.w);
        d[4] = to_tf32(a1.x); d[5] = to_tf32(a1.y); d[6] = to_tf32(a1.z); d[7] = to_tf32(a1.w);
        float4 w0 = *reinterpret_cast<const float4*>(&W[(long long)wr * Kout + nt + wc]);
        float4 w1 = *reinterpret_cast<const float4*>(&W[(long long)wr * Kout + nt + wc + 4]);
        float* e = &Ws[0][wr * PW + wc];
        e[0] = to_tf32(w0.x); e[1] = to_tf32(w0.y); e[2] = to_tf32(w0.z); e[3] = to_tf32(w0.w);
        e[4] = to_tf32(w1.x); e[5] = to_tf32(w1.y); e[6] = to_tf32(w1.z); e[7] = to_tf32(w1.w);
    }
    __syncthreads();

    int buf = 0;
    for (int kt = 0; kt < KIN; kt += 16) {
        bool notlast = (kt + 16 < KIN);
        float4 na0, na1, nw0, nw1;
        if (notlast) {
            na0 = *reinterpret_cast<const float4*>(&Arow[kt + 16 + ak]);
            na1 = *reinterpret_cast<const float4*>(&Arow[kt + 16 + ak + 4]);
            nw0 = *reinterpret_cast<const float4*>(&W[(long long)(kt + 16 + wr) * Kout + nt + wc]);
            nw1 = *reinterpret_cast<const float4*>(&W[(long long)(kt + 16 + wr) * Kout + nt + wc + 4]);
        }
        const float* Ab = As[buf];
        const float* Wb = Ws[buf];
        #pragma unroll
        for (int ks = 0; ks < 16; ks += 8) {
            uint32_t af[2][4];
            #pragma unroll
            for (int mi = 0; mi < 2; mi++) {
                int r0 = m0w + mi * 16 + g;
                af[mi][0] = __float_as_uint(Ab[(r0    ) * PA + ks + t4    ]);
                af[mi][1] = __float_as_uint(Ab[(r0 + 8) * PA + ks + t4    ]);
                af[mi][2] = __float_as_uint(Ab[(r0    ) * PA + ks + t4 + 4]);
                af[mi][3] = __float_as_uint(Ab[(r0 + 8) * PA + ks + t4 + 4]);
            }
            uint32_t bf[8][2];
            #pragma unroll
            for (int ni = 0; ni < 8; ni++) {
                int c0 = n0w + ni * 8 + g;
                bf[ni][0] = __float_as_uint(Wb[(ks + t4    ) * PW + c0]);
                bf[ni][1] = __float_as_uint(Wb[(ks + t4 + 4) * PW + c0]);
            }
            #pragma unroll
            for (int mi = 0; mi < 2; mi++)
                #pragma unroll
                for (int ni = 0; ni < 8; ni++)
                    mma_tf32(acc[mi][ni], af[mi][0], af[mi][1], af[mi][2], af[mi][3],
                             bf[ni][0], bf[ni][1]);
        }
        if (notlast) {
            int nb = buf ^ 1;
            float* d = &As[nb][ar * PA + ak];
            d[0] = to_tf32(na0.x); d[1] = to_tf32(na0.y); d[2] = to_tf32(na0.z); d[3] = to_tf32(na0.w);
            d[4] = to_tf32(na1.x); d[5] = to_tf32(na1.y); d[6] = to_tf32(na1.z); d[7] = to_tf32(na1.w);
            float* e = &Ws[nb][wr * PW + wc];
            e[0] = to_tf32(nw0.x); e[1] = to_tf32(nw0.y); e[2] = to_tf32(nw0.z); e[3] = to_tf32(nw0.w);
            e[4] = to_tf32(nw1.x); e[5] = to_tf32(nw1.y); e[6] = to_tf32(nw1.z); e[7] = to_tf32(nw1.w);
            __syncthreads();
        }
        buf ^= 1;
    }

    #pragma unroll
    for (int mi = 0; mi < 2; mi++) {
        #pragma unroll
        for (int ni = 0; ni < 8; ni++) {
            int row = mt + m0w + mi * 16 + g;
            int col = nt + n0w + ni * 8 + 2 * t4;
            float4 v = acc[mi][ni];
            *reinterpret_cast<float2*>(&C[(long long)row * Kout + col]) = make_float2(v.x, v.y);
            *reinterpret_cast<float2*>(&C[(long long)(row + 8) * Kout + col]) = make_float2(v.z, v.w);
        }
    }
}

// ============================================================
// Kernel 5a: score + rank-sort + two-level scans + coeffs.
// All outputs stored BY ORIGINAL INDEX (every global access coalesced).
// ============================================================
__global__ void __launch_bounds__(512, 2)
sortscan_kernel(const float* __restrict__ h, const float* __restrict__ att,
                int* __restrict__ rank_g, float* __restrict__ e1_g,
                float* __restrict__ e2_g, float4* __restrict__ pkc_g) {
    int bh = blockIdx.x;
    int b = bh >> 2, hd = bh & 3;
    int i = threadIdx.x;
    int w = i >> 5, l = i & 31;

    __shared__ float satt[128];
    __shared__ float svi[N_];          // b-values by original index
    __shared__ float svs[N_];          // sorted values
    __shared__ float sP1[N_ + 1], sP2[N_ + 1];
    __shared__ float red[16];
    __shared__ float tot1[16], tot2[16];
    __shared__ float base1[16], base2[16];
    __shared__ float smb;

    if (i < 128) satt[i] = att[hd * 128 + i];
    __syncthreads();

    // scores
    const float4* hrow = reinterpret_cast<const float4*>(&h[((long long)(b * N_ + i)) * C_ + hd * 64]);
    float a = 0.f, bval = 0.f;
    #pragma unroll
    for (int q = 0; q < 16; q++) {
        float4 v = hrow[q];
        float4 w1 = *reinterpret_cast<const float4*>(&satt[q * 4]);
        float4 w2 = *reinterpret_cast<const float4*>(&satt[64 + q * 4]);
        a    += v.x * w1.x + v.y * w1.y + v.z * w1.z + v.w * w1.w;
        bval += v.x * w2.x + v.y * w2.y + v.z * w2.z + v.w * w2.w;
    }

    // block max of bval
    float mx = bval;
    #pragma unroll
    for (int off = 16; off >= 1; off >>= 1)
        mx = fmaxf(mx, __shfl_xor_sync(0xffffffffu, mx, off));
    if (l == 0) red[w] = mx;
    __syncthreads();
    if (i == 0) {
        float m = red[0];
        #pragma unroll
        for (int c = 1; c < 16; c++) m = fmaxf(m, red[c]);
        smb = m;
    }
    __syncthreads();
    float mb = smb;
    float v = bval - mb;
    svi[i] = v;
    __syncthreads();

    // rank-by-count (stable via index tie-break); broadcast smem reads
    int rank = 0;
    const float4* svi4 = reinterpret_cast<const float4*>(svi);
    #pragma unroll 4
    for (int q = 0; q < N_ / 4; q++) {
        float4 u = svi4[q];
        int j0 = q * 4;
        rank += (u.x < v) || (u.x == v && (j0    ) < i);
        rank += (u.y < v) || (u.y == v && (j0 + 1) < i);
        rank += (u.z < v) || (u.z == v && (j0 + 2) < i);
        rank += (u.w < v) || (u.w == v && (j0 + 3) < i);
    }
    svs[rank] = v;
    __syncthreads();

    // per-original-index exp weights (coalesced stores)
    e1_g[bh * N_ + i] = __expf(v);
    e2_g[bh * N_ + i] = __expf(0.2f * v);
    rank_g[bh * N_ + i] = rank;

    // scans by sorted position k = tid
    float vk = svs[i];
    float e1k = __expf(vk);
    float e2k = __expf(0.2f * vk);
    float p1 = e1k, p2 = e2k;
    #pragma unroll
    for (int off = 1; off < 32; off <<= 1) {
        float nu = __shfl_up_sync(0xffffffffu, p2, off);
        float nd = __shfl_down_sync(0xffffffffu, p1, off);
        if (l >= off)     p2 += nu;
        if (l + off < 32) p1 += nd;
    }
    if (l == 31) tot2[w] = p2;
    if (l == 0)  tot1[w] = p1;
    __syncthreads();
    if (i == 0) {
        float pre = 0.f;
        #pragma unroll
        for (int c = 0; c < 16; c++) { base2[c] = pre; pre += tot2[c]; }
    } else if (i == 32) {
        float s = 0.f;
        #pragma unroll
        for (int c = 15; c >= 0; c--) { base1[c] = s; s += tot1[c]; }
    }
    __syncthreads();
    sP2[i + 1] = base2[w] + p2;
    sP1[i]     = base1[w] + p1;
    if (i == 0) { sP2[0] = 0.f; sP1[N_] = 0.f; }
    __syncthreads();

    // per-i threshold + coeffs (coalesced store by i)
    float thr = -a - mb;
    int lo = 0, hi = N_;
    while (lo < hi) {
        int mid = (lo + hi) >> 1;
        if (svs[mid] > thr) hi = mid; else lo = mid + 1;
    }
    int t = lo;
    float s = a + mb;
    float m = s > 0.f ? s : 0.2f * s;
    float c1v = __expf(s - m);
    float c2v = __expf(0.2f * s - m);
    float sci = a + bval;
    float lsci = sci > 0.f ? sci : 0.2f * sci;
    float ns = __expf(lsci - m);
    float Z = c1v * sP1[t] + c2v * sP2[t] - ns;
    float rz = 1.f / fmaxf(Z, 1e-35f);
    pkc_g[bh * N_ + i] = make_float4(c1v * rz, c2v * rz, ns * rz, __int_as_float(t));
}

// ============================================================
// Kernel 5b: FUSED scans + emit, f-sliced, thread = ORIGINAL index.
// All global loads/stores coalesced; sort permutation applied in smem
// (scatter to row rank[i], scan rows k=tid, lookup row t at emit).
// ============================================================
__global__ void __launch_bounds__(512, 2)
fusedscan_kernel(const float* __restrict__ h,
                 const int* __restrict__ rank_g,
                 const float* __restrict__ e1_g, const float* __restrict__ e2_g,
                 const float4* __restrict__ pkc_g,
                 float* __restrict__ out, int dorelu) {
    __shared__ float V1h[N_ + 1][PV];
    __shared__ float V2h[N_ + 1][PV];
    __shared__ float tot1[16][FQ], tot2[16][FQ];
    __shared__ float suf1[17][FQ], pre2[17][FQ];

    int bh = blockIdx.x;
    int fo = blockIdx.y * FQ;
    int b = bh >> 2, hd = bh & 3;
    int tid = threadIdx.x;
    int w = tid >> 5, l = tid & 31;

    int r = rank_g[bh * N_ + tid];          // coalesced
    float4 pk = pkc_g[bh * N_ + tid];       // coalesced
    float e1 = e1_g[bh * N_ + tid];         // coalesced
    float e2 = e2_g[bh * N_ + tid];         // coalesced
    if (tid < FQ) { V1h[N_][tid] = 0.f; V2h[N_][tid] = 0.f; }

    // coalesced h load: my own row slice
    const float* hb = h + ((long long)(b * N_ + tid)) * C_ + hd * 64 + fo;
    float hv[FQ];
    {
        float4 v0 = *reinterpret_cast<const float4*>(hb);
        float4 v1 = *reinterpret_cast<const float4*>(hb + 4);
        hv[0] = v0.x; hv[1] = v0.y; hv[2] = v0.z; hv[3] = v0.w;
        hv[4] = v1.x; hv[5] = v1.y; hv[6] = v1.z; hv[7] = v1.w;
    }

    // scatter contributions into sorted rows (smem only)
    #pragma unroll
    for (int f = 0; f < FQ; f++) {
        V1h[r][f] = e1 * hv[f];
        V2h[r][f] = e2 * hv[f];
    }
    __syncthreads();

    // pass 1: chunk-local scans on sorted rows k = tid (pitch-9: conflict-free)
    float p1[FQ], p2[FQ], x1[FQ], x2[FQ];
    #pragma unroll
    for (int f = 0; f < FQ; f++) {
        x1[f] = V1h[tid][f]; x2[f] = V2h[tid][f];
        p1[f] = x1[f];       p2[f] = x2[f];
    }
    #pragma unroll
    for (int off = 1; off < 32; off <<= 1) {
        #pragma unroll
        for (int f = 0; f < FQ; f++) {
            float nu = __shfl_up_sync(0xffffffffu, p2[f], off);
            float nd = __shfl_down_sync(0xffffffffu, p1[f], off);
            if (l >= off)     p2[f] += nu;
            if (l + off < 32) p1[f] += nd;
        }
    }
    #pragma unroll
    for (int f = 0; f < FQ; f++) {
        V2h[tid][f] = p2[f] - x2[f];   // exclusive prefix (chunk-local)
        V1h[tid][f] = p1[f];           // inclusive suffix (chunk-local)
    }
    if (l == 31) {
        #pragma unroll
        for (int f = 0; f < FQ; f++) tot2[w][f] = p2[f];
    }
    if (l == 0) {
        #pragma unroll
        for (int f = 0; f < FQ; f++) tot1[w][f] = p1[f];
    }
    __syncthreads();

    // pass 2: chunk bases
    if (tid < FQ) {
        int f = tid;
        float pre = 0.f;
        #pragma unroll
        for (int c = 0; c < 16; c++) { pre2[c][f] = pre; pre += tot2[c][f]; }
        pre2[16][f] = pre;
    } else if (tid < 2 * FQ) {
        int f = tid - FQ;
        float s = 0.f;
        suf1[16][f] = 0.f;
        #pragma unroll
        for (int c = 15; c >= 0; c--) { suf1[c][f] = s; s += tot1[c][f]; }
    }
    __syncthreads();

    // pass 3: emit my own row (coalesced store)
    {
        int t = __float_as_int(pk.w);
        float c1 = pk.x, c2 = pk.y, ns = pk.z;
        int tc = t >> 5;
        float o[FQ];
        #pragma unroll
        for (int f = 0; f < FQ; f++) {
            float v1 = V1h[t][f] + suf1[tc][f];
            float v2 = V2h[t][f] + pre2[tc][f];
            float val = c1 * v1 + c2 * v2 - ns * hv[f];
            o[f] = dorelu ? fmaxf(val, 0.f) : val;
        }
        float* outp = out + ((long long)(b * N_ + tid)) * C_ + hd * 64 + fo;
        *reinterpret_cast<float4*>(outp)     = make_float4(o[0], o[1], o[2], o[3]);
        *reinterpret_cast<float4*>(outp + 4) = make_float4(o[4], o[5], o[6], o[7]);
    }
}

// ============================================================
// launch
// ============================================================
extern "C" void kernel_launch(void* const* d_in, const int* in_sizes, int n_in,
                              void* d_out, int out_size) {
    int off = (n_in >= 16) ? 1 : 0;
    const int*   player = (const int*)  d_in[0];
    const int*   shot   = (const int*)  d_in[1];
    const float* Ax     = (const float*)d_in[2];
    const float* Ay     = (const float*)d_in[3];
    const float* Bx     = (const float*)d_in[4];
    const float* By     = (const float*)d_in[5];
    const float* emb    = (const float*)d_in[6 + off];
    const float* Wc     = (const float*)d_in[7 + off];
    const float* bc     = (const float*)d_in[8 + off];
    const float* Wm     = (const float*)d_in[9 + off];
    const float* bm     = (const float*)d_in[10 + off];
    const float* lin1   = (const float*)d_in[11 + off];
    const float* att1   = (const float*)d_in[12 + off];
    const float* lin2   = (const float*)d_in[13 + off];
    const float* att2   = (const float*)d_in[14 + off];

    float* out_ne  = (float*)d_out;
    float* out_adj = out_ne + NE_ELEMS;

    float *px, *ph, *po1, *pe1, *pe2;
    int *prank;
    float4 *ppkc;
    cudaGetSymbolAddress((void**)&px,  g_x);
    cudaGetSymbolAddress((void**)&ph,  g_h);
    cudaGetSymbolAddress((void**)&po1, g_o1);
    cudaGetSymbolAddress((void**)&pe1, g_e1);
    cudaGetSymbolAddress((void**)&pe2, g_e2);
    cudaGetSymbolAddress((void**)&prank, g_rank);
    cudaGetSymbolAddress((void**)&ppkc, g_pkc);

    int need_adj = (out_size >= NE_ELEMS + ADJ_ELEMS) ? 1 : 0;

    feat_kernel<<<B_ * 16, 256>>>(player, Ax, Ay, Bx, By, emb, Wc, bc, Wm, bm, px);

    dim3 ggrid1(2, MROWS + (need_adj ? FILL_A / 2 : 0));
    dim3 ggrid2(2, MROWS + (need_adj ? FILL_B / 2 : 0));
    dim3 fgrid(BH_, F_ / FQ);

    // ---- layer 1 ----
    gemm_fill_kernel<HID><<<ggrid1, 256>>>(px, lin1, ph, out_adj, 0);
    sortscan_kernel<<<BH_, N_>>>(ph, att1, prank, pe1, pe2, ppkc);
    fusedscan_kernel<<<fgrid, 512>>>(ph, prank, pe1, pe2, ppkc, po1, 1);

    // ---- layer 2 ----
    gemm_fill_kernel<C_><<<ggrid2, 256>>>(po1, lin2, ph, out_adj, FILL_A);
    sortscan_kernel<<<BH_, N_>>>(ph, att2, prank, pe1, pe2, ppkc);
    fusedscan_kernel<<<fgrid, 512>>>(ph, prank, pe1, pe2, ppkc, out_ne, 0);

    if (need_adj) scatter_kernel<<<(B_ * S_ + 255) / 256, 256>>>(shot, out_adj);
}

// round 11
// speedup vs baseline: 1.0349x; 1.0349x over previous
#include <cuda_runtime.h>
#include <cstdint>

// ---------------- problem constants ----------------
#define B_    32
#define E_    256
#define N_    512
#define HID   64
#define H_    4
#define F_    64
#define C_    256
#define S_    255
#define BH_   (B_*H_)
#define NE_ELEMS (B_*N_*C_)
#define ADJ_ELEMS (B_*14*N_*N_)
#define MROWS ((B_*N_)/128)

#define PA 20
#define PW 136
#define FQ 8
#define PV 9

// ---------------- scratch ----------------
__device__ float  g_x  [B_*N_*HID];
__device__ float  g_h  [B_*N_*C_];
__device__ float  g_o1 [B_*N_*C_];
__device__ int    g_sidx[BH_*N_];
__device__ float  g_e1 [BH_*N_];
__device__ float  g_e2 [BH_*N_];
__device__ int    g_t  [BH_*N_];
__device__ float  g_c1 [BH_*N_];
__device__ float  g_c2 [BH_*N_];
__device__ float  g_ns [BH_*N_];

__device__ __forceinline__ float to_tf32(float x) {
    float r; asm("cvt.rna.tf32.f32 %0, %1;" : "=f"(r) : "f"(x)); return r;
}

__device__ __forceinline__ void mma_tf32(float4& d,
                                         uint32_t a0, uint32_t a1, uint32_t a2, uint32_t a3,
                                         uint32_t b0, uint32_t b1) {
    asm("mma.sync.aligned.m16n8k8.row.col.f32.tf32.tf32.f32 "
        "{%0,%1,%2,%3},{%4,%5,%6,%7},{%8,%9},{%0,%1,%2,%3};"
        : "+f"(d.x), "+f"(d.y), "+f"(d.z), "+f"(d.w)
        : "r"(a0), "r"(a1), "r"(a2), "r"(a3), "r"(b0), "r"(b1));
}

// ============================================================
// Kernel 1a: standalone adjacency fill (32 elems / thread).
// ============================================================
__global__ void fill_kernel(float* __restrict__ out) {
    int t = threadIdx.x;
    int n  = blockIdx.x * 16 + (t >> 4);
    int m0 = (t & 15) * 32;
    int r = blockIdx.y, b = blockIdx.z;
    float* p = out + ((((long long)b * 14 + r) * N_ + n) << 9) + m0;
    float4* p4 = reinterpret_cast<float4*>(p);

    if (r < 13) {
        float4 z = make_float4(0.f, 0.f, 0.f, 0.f);
        #pragma unroll
        for (int q = 0; q < 8; q++) __stcs(p4 + q, z);
        if (r >= 11) {
            int cu = n + 2;
            if (cu < N_ && cu >= m0 && cu < m0 + 32) {
                int rel = ((n & 3) == 0 || (n & 3) == 3) ? 11 : 12;
                if (rel == r) p[cu - m0] = 1.f;
            }
            int cd = n - 2;
            if (cd >= 0 && cd >= m0 && cd < m0 + 32) {
                int pp = n - 2;
                int rel = ((pp & 3) == 0 || (pp & 3) == 3) ? 11 : 12;
                if (rel == r) p[cd - m0] = 1.f;
            }
        }
        return;
    }
    if (n + 3 < m0 || n - 3 >= m0 + 32) {
        float4 o1 = make_float4(1.f, 1.f, 1.f, 1.f);
        #pragma unroll
        for (int q = 0; q < 8; q++) __stcs(p4 + q, o1);
        return;
    }
    int sp1 = -1, sp2 = -1;
    int nm = n & 3;
    if (nm == 0) {
        if (n <= 508) sp1 = n + 3;
        if (n >= 4)   sp2 = n - 1;
    } else if (nm == 3) {
        if (n <= 507) sp1 = n + 1;
        sp2 = n - 3;
    }
    float vals[32];
    #pragma unroll
    for (int q = 0; q < 32; q++) {
        int m = m0 + q;
        bool zero = (m == n) | (m == n - 2) | (m == n + 2) | (m == sp1) | (m == sp2);
        vals[q] = zero ? 0.f : 1.f;
    }
    #pragma unroll
    for (int q = 0; q < 8; q++)
        __stcs(p4 + q, make_float4(vals[4*q], vals[4*q+1], vals[4*q+2], vals[4*q+3]));
}

__global__ void scatter_kernel(const int* __restrict__ shot, float* __restrict__ out) {
    int idx = blockIdx.x * 256 + threadIdx.x;
    if (idx >= B_ * S_) return;
    int b = idx / S_, s = idx % S_;
    int r = shot[idx];
    int i, j;
    if ((s & 1) == 0) { i = 2 * s;     j = 2 * s + 3; }
    else              { i = 2 * s + 1; j = 2 * s + 2; }
    long long base = ((long long)b * 14 + r) * (N_ * N_);
    out[base + (long long)i * N_ + j] = 1.f;
    out[base + (long long)j * N_ + i] = 1.f;
}

// ============================================================
// Kernel 2: node features.
// ============================================================
__global__ void feat_kernel(const int* __restrict__ player,
                            const float* __restrict__ Ax, const float* __restrict__ Ay,
                            const float* __restrict__ Bx, const float* __restrict__ By,
                            const float* __restrict__ emb,
                            const float* __restrict__ Wc, const float* __restrict__ bc,
                            const float* __restrict__ Wm, const float* __restrict__ bm,
                            float* __restrict__ x) {
    __shared__ float feat[32][64];
    __shared__ float wms[64 * 64];
    int blk = blockIdx.x;
    int b = blk >> 4;
    int n0 = (blk & 15) * 32;
    int tid = threadIdx.x;

    #pragma unroll
    for (int it = 0; it < 16; it++) wms[it * 256 + tid] = Wm[it * 256 + tid];

    #pragma unroll
    for (int it = 0; it < 8; it++) {
        int o = it * 256 + tid;
        int nl = o >> 6, c = o & 63;
        int n = n0 + nl;
        int e = n >> 1;
        float val;
        if (c < 32) {
            float cx, cy;
            if ((n & 1) == 0) { cx = Ax[b * E_ + e]; cy = Ay[b * E_ + e]; }
            else              { cx = Bx[b * E_ + e]; cy = By[b * E_ + e]; }
            val = fmaxf(cx * Wc[c] + cy * Wc[32 + c] + bc[c], 0.f);
        } else {
            int pid = player[b * 2 + (n & 1)];
            val = emb[pid * 32 + (c - 32)];
        }
        feat[nl][c] = val;
    }
    __syncthreads();

    #pragma unroll
    for (int it = 0; it < 8; it++) {
        int o = it * 256 + tid;
        int nl = o >> 6, k = o & 63;
        float acc = bm[k];
        #pragma unroll
        for (int c = 0; c < 64; c++) acc += feat[nl][c] * wms[c * 64 + k];
        x[(b * N_ + n0 + nl) * HID + k] = acc;
    }
}

// ============================================================
// Kernel 3: pure tf32-MMA SGEMM (128x128 tile, 8 warps 4x2).
// ============================================================
template<int KIN>
__global__ void __launch_bounds__(256, 2)
gemm_kernel(const float* __restrict__ A, const float* __restrict__ W,
            float* __restrict__ C) {
    __shared__ float As[2][128 * PA];
    __shared__ float Ws[2][16 * PW];
    const int Kout = C_;
    int tid = threadIdx.x;
    int mt = blockIdx.y * 128, nt = blockIdx.x * 128;
    int wid = tid >> 5, lane = tid & 31;
    int g = lane >> 2, t4 = lane & 3;
    int m0w = (wid >> 1) * 32;
    int n0w = (wid & 1) * 64;

    int ar = tid >> 1;
    int ak = (tid & 1) * 8;
    int wr = tid >> 4;
    int wc = (tid & 15) * 8;

    float4 acc[2][8];
    #pragma unroll
    for (int mi = 0; mi < 2; mi++)
        #pragma unroll
        for (int ni = 0; ni < 8; ni++) acc[mi][ni] = make_float4(0.f, 0.f, 0.f, 0.f);

    const float* Arow = &A[(long long)(mt + ar) * KIN];

    {
        float4 a0 = *reinterpret_cast<const float4*>(&Arow[ak]);
        float4 a1 = *reinterpret_cast<const float4*>(&Arow[ak + 4]);
        float* d = &As[0][ar * PA + ak];
        d[0] = to_tf32(a0.x); d[1] = to_tf32(a0.y); d[2] = to_tf32(a0.z); d[3] = to_tf32(a0.w);
        d[4] = to_tf32(a1.x); d[5] = to_tf32(a1.y); d[6] = to_tf32(a1.z); d[7] = to_tf32(a1.w);
        float4 w0 = *reinterpret_cast<const float4*>(&W[(long long)wr * Kout + nt + wc]);
        float4 w1 = *reinterpret_cast<const float4*>(&W[(long long)wr * Kout + nt + wc + 4]);
        float* e = &Ws[0][wr * PW + wc];
        e[0] = to_tf32(w0.x); e[1] = to_tf32(w0.y); e[2] = to_tf32(w0.z); e[3] = to_tf32(w0.w);
        e[4] = to_tf32(w1.x); e[5] = to_tf32(w1.y); e[6] = to_tf32(w1.z); e[7] = to_tf32(w1.w);
    }
    __syncthreads();

    int buf = 0;
    for (int kt = 0; kt < KIN; kt += 16) {
        bool notlast = (kt + 16 < KIN);
        float4 na0, na1, nw0, nw1;
        if (notlast) {
            na0 = *reinterpret_cast<const float4*>(&Arow[kt + 16 + ak]);
            na1 = *reinterpret_cast<const float4*>(&Arow[kt + 16 + ak + 4]);
            nw0 = *reinterpret_cast<const float4*>(&W[(long long)(kt + 16 + wr) * Kout + nt + wc]);
            nw1 = *reinterpret_cast<const float4*>(&W[(long long)(kt + 16 + wr) * Kout + nt + wc + 4]);
        }
        const float* Ab = As[buf];
        const float* Wb = Ws[buf];
        #pragma unroll
        for (int ks = 0; ks < 16; ks += 8) {
            uint32_t af[2][4];
            #pragma unroll
            for (int mi = 0; mi < 2; mi++) {
                int r0 = m0w + mi * 16 + g;
                af[mi][0] = __float_as_uint(Ab[(r0    ) * PA + ks + t4    ]);
                af[mi][1] = __float_as_uint(Ab[(r0 + 8) * PA + ks + t4    ]);
                af[mi][2] = __float_as_uint(Ab[(r0    ) * PA + ks + t4 + 4]);
                af[mi][3] = __float_as_uint(Ab[(r0 + 8) * PA + ks + t4 + 4]);
            }
            uint32_t bf[8][2];
            #pragma unroll
            for (int ni = 0; ni < 8; ni++) {
                int c0 = n0w + ni * 8 + g;
                bf[ni][0] = __float_as_uint(Wb[(ks + t4    ) * PW + c0]);
                bf[ni][1] = __float_as_uint(Wb[(ks + t4 + 4) * PW + c0]);
            }
            #pragma unroll
            for (int mi = 0; mi < 2; mi++)
                #pragma unroll
                for (int ni = 0; ni < 8; ni++)
                    mma_tf32(acc[mi][ni], af[mi][0], af[mi][1], af[mi][2], af[mi][3],
                             bf[ni][0], bf[ni][1]);
        }
        if (notlast) {
            int nb = buf ^ 1;
            float* d = &As[nb][ar * PA + ak];
            d[0] = to_tf32(na0.x); d[1] = to_tf32(na0.y); d[2] = to_tf32(na0.z); d[3] = to_tf32(na0.w);
            d[4] = to_tf32(na1.x); d[5] = to_tf32(na1.y); d[6] = to_tf32(na1.z); d[7] = to_tf32(na1.w);
            float* e = &Ws[nb][wr * PW + wc];
            e[0] = to_tf32(nw0.x); e[1] = to_tf32(nw0.y); e[2] = to_tf32(nw0.z); e[3] = to_tf32(nw0.w);
            e[4] = to_tf32(nw1.x); e[5] = to_tf32(nw1.y); e[6] = to_tf32(nw1.z); e[7] = to_tf32(nw1.w);
            __syncthreads();
        }
        buf ^= 1;
    }

    #pragma unroll
    for (int mi = 0; mi < 2; mi++) {
        #pragma unroll
        for (int ni = 0; ni < 8; ni++) {
            int row = mt + m0w + mi * 16 + g;
            int col = nt + n0w + ni * 8 + 2 * t4;
            float4 v = acc[mi][ni];
            *reinterpret_cast<float2*>(&C[(long long)row * Kout + col]) = make_float2(v.x, v.y);
            *reinterpret_cast<float2*>(&C[(long long)(row + 8) * Kout + col]) = make_float2(v.z, v.w);
        }
    }
}

// ============================================================
// Kernel 5a: fused score + bitonic sort + scalar scans + coeffs (R8).
// ============================================================
__global__ void sortscan_kernel(const float* __restrict__ h, const float* __restrict__ att,
                                int* __restrict__ sidx_g, float* __restrict__ e1_g,
                                float* __restrict__ e2_g, int* __restrict__ t_g,
                                float* __restrict__ c1_g, float* __restrict__ c2_g,
                                float* __restrict__ ns_g) {
    int bh = blockIdx.x;
    int b = bh >> 2, hd = bh & 3;
    int i = threadIdx.x;
    __shared__ float satt[128];
    __shared__ float sv[N_];
    __shared__ int   si[N_];
    __shared__ float sP1[N_ + 1], sP2[N_ + 1];
    __shared__ float sbuf[N_];

    if (i < 128) satt[i] = att[hd * 128 + i];
    __syncthreads();

    const float4* hrow = reinterpret_cast<const float4*>(&h[((long long)(b * N_ + i)) * C_ + hd * 64]);
    float a = 0.f, bval = 0.f;
    #pragma unroll
    for (int q = 0; q < 16; q++) {
        float4 v = hrow[q];
        float4 w1 = *reinterpret_cast<const float4*>(&satt[q * 4]);
        float4 w2 = *reinterpret_cast<const float4*>(&satt[64 + q * 4]);
        a    += v.x * w1.x + v.y * w1.y + v.z * w1.z + v.w * w1.w;
        bval += v.x * w2.x + v.y * w2.y + v.z * w2.z + v.w * w2.w;
    }

    sbuf[i] = bval; __syncthreads();
    #pragma unroll
    for (int o = 256; o > 0; o >>= 1) {
        if (i < o) sbuf[i] = fmaxf(sbuf[i], sbuf[i + o]);
        __syncthreads();
    }
    float mb = sbuf[0];
    __syncthreads();

    sv[i] = bval - mb; si[i] = i;
    __syncthreads();
    for (int k = 2; k <= N_; k <<= 1) {
        for (int j = k >> 1; j > 0; j >>= 1) {
            int l = i ^ j;
            if (l > i) {
                bool up = ((i & k) == 0);
                float v0 = sv[i], v1 = sv[l];
                if ((v0 > v1) == up) {
                    sv[i] = v1; sv[l] = v0;
                    int t0 = si[i]; si[i] = si[l]; si[l] = t0;
                }
            }
            __syncthreads();
        }
    }

    float e1 = __expf(sv[i]);
    float e2 = __expf(0.2f * sv[i]);

    sbuf[i] = e2; __syncthreads();
    for (int o = 1; o < N_; o <<= 1) {
        float v = sbuf[i];
        if (i >= o) v += sbuf[i - o];
        __syncthreads();
        sbuf[i] = v;
        __syncthreads();
    }
    sP2[i + 1] = sbuf[i];
    if (i == 0) sP2[0] = 0.f;
    __syncthreads();
    sbuf[i] = e1; __syncthreads();
    for (int o = 1; o < N_; o <<= 1) {
        float v = sbuf[i];
        if (i + o < N_) v += sbuf[i + o];
        __syncthreads();
        sbuf[i] = v;
        __syncthreads();
    }
    sP1[i] = sbuf[i];
    if (i == 0) sP1[N_] = 0.f;
    __syncthreads();

    sidx_g[bh * N_ + i] = si[i];
    e1_g[bh * N_ + i] = e1;
    e2_g[bh * N_ + i] = e2;

    float thr = -a - mb;
    int lo = 0, hi = N_;
    while (lo < hi) {
        int mid = (lo + hi) >> 1;
        if (sv[mid] > thr) hi = mid; else lo = mid + 1;
    }
    int t = lo;
    float s = a + mb;
    float m = s > 0.f ? s : 0.2f * s;
    float c1v = __expf(s - m);
    float c2v = __expf(0.2f * s - m);
    float sci = a + bval;
    float lsci = sci > 0.f ? sci : 0.2f * sci;
    float ns = __expf(lsci - m);
    float Z = c1v * sP1[t] + c2v * sP2[t] - ns;
    float rz = 1.f / fmaxf(Z, 1e-35f);
    t_g [bh * N_ + i] = t;
    c1_g[bh * N_ + i] = c1v * rz;
    c2_g[bh * N_ + i] = c2v * rz;
    ns_g[bh * N_ + i] = ns * rz;
}

// ============================================================
// Kernel 5b: FUSED vector scans + emit, f-sliced (R8 version).
// ============================================================
__global__ void __launch_bounds__(512, 2)
fusedscan_kernel(const float* __restrict__ h,
                 const int* __restrict__ sidx_g,
                 const float* __restrict__ e1_g, const float* __restrict__ e2_g,
                 const int* __restrict__ t_g, const float* __restrict__ c1_g,
                 const float* __restrict__ c2_g, const float* __restrict__ ns_g,
                 float* __restrict__ out, int dorelu) {
    __shared__ float V1h[N_ + 1][PV];
    __shared__ float V2h[N_ + 1][PV];
    __shared__ float tot1[16][FQ], tot2[16][FQ];
    __shared__ float suf1[17][FQ], pre2[17][FQ];
    __shared__ int   sIdx[N_];
    __shared__ int   sT[N_];
    __shared__ float sC1[N_], sC2[N_], sNS[N_];

    int bh = blockIdx.x;
    int fo = blockIdx.y * FQ;
    int b = bh >> 2, hd = bh & 3;
    int tid = threadIdx.x;
    int w = tid >> 5, l = tid & 31;

    int myIdx = sidx_g[bh * N_ + tid];
    sIdx[tid] = myIdx;
    sT[tid]   = t_g [bh * N_ + tid];
    sC1[tid]  = c1_g[bh * N_ + tid];
    sC2[tid]  = c2_g[bh * N_ + tid];
    sNS[tid]  = ns_g[bh * N_ + tid];
    float ev1 = e1_g[bh * N_ + tid];
    float ev2 = e2_g[bh * N_ + tid];
    if (tid < FQ) { V1h[N_][tid] = 0.f; V2h[N_][tid] = 0.f; }

    const float* hb = h + (long long)b * N_ * C_ + hd * 64 + fo;
    float hv[FQ];
    {
        float4 v0 = *reinterpret_cast<const float4*>(&hb[(long long)myIdx * C_]);
        float4 v1 = *reinterpret_cast<const float4*>(&hb[(long long)myIdx * C_ + 4]);
        hv[0] = v0.x; hv[1] = v0.y; hv[2] = v0.z; hv[3] = v0.w;
        hv[4] = v1.x; hv[5] = v1.y; hv[6] = v1.z; hv[7] = v1.w;
    }

    float p1[FQ], p2[FQ];
    #pragma unroll
    for (int f = 0; f < FQ; f++) { p1[f] = ev1 * hv[f]; p2[f] = ev2 * hv[f]; }
    #pragma unroll
    for (int off = 1; off < 32; off <<= 1) {
        #pragma unroll
        for (int f = 0; f < FQ; f++) {
            float nu = __shfl_up_sync(0xffffffffu, p2[f], off);
            float nd = __shfl_down_sync(0xffffffffu, p1[f], off);
            if (l >= off)     p2[f] += nu;
            if (l + off < 32) p1[f] += nd;
        }
    }
    #pragma unroll
    for (int f = 0; f < FQ; f++) {
        V2h[tid][f] = p2[f] - ev2 * hv[f];
        V1h[tid][f] = p1[f];
    }
    if (l == 31) {
        #pragma unroll
        for (int f = 0; f < FQ; f++) tot2[w][f] = p2[f];
    }
    if (l == 0) {
        #pragma unroll
        for (int f = 0; f < FQ; f++) tot1[w][f] = p1[f];
    }
    __syncthreads();

    if (tid < FQ) {
        int f = tid;
        float pre = 0.f;
        #pragma unroll
        for (int c = 0; c < 16; c++) { pre2[c][f] = pre; pre += tot2[c][f]; }
        pre2[16][f] = pre;
    } else if (tid < 2 * FQ) {
        int f = tid - FQ;
        float s = 0.f;
        suf1[16][f] = 0.f;
        #pragma unroll
        for (int c = 15; c >= 0; c--) { suf1[c][f] = s; s += tot1[c][f]; }
    }
    __syncthreads();

    {
        int i = myIdx;
        int t = sT[i];
        float c1 = sC1[i], c2 = sC2[i], ns = sNS[i];
        int tc = t >> 5;
        float o[FQ];
        #pragma unroll
        for (int f = 0; f < FQ; f++) {
            float v1 = V1h[t][f] + suf1[tc][f];
            float v2 = V2h[t][f] + pre2[tc][f];
            float val = c1 * v1 + c2 * v2 - ns * hv[f];
            o[f] = dorelu ? fmaxf(val, 0.f) : val;
        }
        float* outp = out + ((long long)(b * N_ + i)) * C_ + hd * 64 + fo;
        *reinterpret_cast<float4*>(outp)     = make_float4(o[0], o[1], o[2], o[3]);
        *reinterpret_cast<float4*>(outp + 4) = make_float4(o[4], o[5], o[6], o[7]);
    }
}

// ============================================================
// launch — adjacency fill forked onto a second captured stream so it
// overlaps the whole GAT chain. Streams/events created once (first call
// is the uncaptured correctness run); identical work every call.
// ============================================================
extern "C" void kernel_launch(void* const* d_in, const int* in_sizes, int n_in,
                              void* d_out, int out_size) {
    static cudaStream_t s2 = nullptr;
    static cudaEvent_t evFork = nullptr, evJoin = nullptr;
    if (s2 == nullptr) {
        cudaStreamCreateWithFlags(&s2, cudaStreamNonBlocking);
        cudaEventCreateWithFlags(&evFork, cudaEventDisableTiming);
        cudaEventCreateWithFlags(&evJoin, cudaEventDisableTiming);
    }

    int off = (n_in >= 16) ? 1 : 0;
    const int*   player = (const int*)  d_in[0];
    const int*   shot   = (const int*)  d_in[1];
    const float* Ax     = (const float*)d_in[2];
    const float* Ay     = (const float*)d_in[3];
    const float* Bx     = (const float*)d_in[4];
    const float* By     = (const float*)d_in[5];
    const float* emb    = (const float*)d_in[6 + off];
    const float* Wc     = (const float*)d_in[7 + off];
    const float* bc     = (const float*)d_in[8 + off];
    const float* Wm     = (const float*)d_in[9 + off];
    const float* bm     = (const float*)d_in[10 + off];
    const float* lin1   = (const float*)d_in[11 + off];
    const float* att1   = (const float*)d_in[12 + off];
    const float* lin2   = (const float*)d_in[13 + off];
    const float* att2   = (const float*)d_in[14 + off];

    float* out_ne  = (float*)d_out;
    float* out_adj = out_ne + NE_ELEMS;

    float *px, *ph, *po1;
    float *pe1, *pe2, *pc1, *pc2, *pns;
    int *psidx, *pt;
    cudaGetSymbolAddress((void**)&px,  g_x);
    cudaGetSymbolAddress((void**)&ph,  g_h);
    cudaGetSymbolAddress((void**)&po1, g_o1);
    cudaGetSymbolAddress((void**)&psidx, g_sidx);
    cudaGetSymbolAddress((void**)&pe1, g_e1);
    cudaGetSymbolAddress((void**)&pe2, g_e2);
    cudaGetSymbolAddress((void**)&pt,  g_t);
    cudaGetSymbolAddress((void**)&pc1, g_c1);
    cudaGetSymbolAddress((void**)&pc2, g_c2);
    cudaGetSymbolAddress((void**)&pns, g_ns);

    int need_adj = (out_size >= NE_ELEMS + ADJ_ELEMS) ? 1 : 0;

    // ---- fork: adjacency branch on s2, overlapping the GAT chain ----
    if (need_adj) {
        cudaEventRecord(evFork, 0);
        cudaStreamWaitEvent(s2, evFork, 0);
        fill_kernel<<<dim3(32, 14, 32), 256, 0, s2>>>(out_adj);
        scatter_kernel<<<(B_ * S_ + 255) / 256, 256, 0, s2>>>(shot, out_adj);
        cudaEventRecord(evJoin, s2);
    }

    // ---- GAT chain on default stream ----
    feat_kernel<<<B_ * 16, 256>>>(player, Ax, Ay, Bx, By, emb, Wc, bc, Wm, bm, px);

    dim3 ggrid(2, MROWS);
    dim3 fgrid(BH_, F_ / FQ);

    gemm_kernel<HID><<<ggrid, 256>>>(px, lin1, ph);
    sortscan_kernel<<<BH_, N_>>>(ph, att1, psidx, pe1, pe2, pt, pc1, pc2, pns);
    fusedscan_kernel<<<fgrid, 512>>>(ph, psidx, pe1, pe2, pt, pc1, pc2, pns, po1, 1);

    gemm_kernel<C_><<<ggrid, 256>>>(po1, lin2, ph);
    sortscan_kernel<<<BH_, N_>>>(ph, att2, psidx, pe1, pe2, pt, pc1, pc2, pns);
    fusedscan_kernel<<<fgrid, 512>>>(ph, psidx, pe1, pe2, pt, pc1, pc2, pns, out_ne, 0);

    // ---- join ----
    if (need_adj) cudaStreamWaitEvent(0, evJoin, 0);
}

// round 12
// speedup vs baseline: 1.1094x; 1.0720x over previous
#include <cuda_runtime.h>
#include <cstdint>

// ---------------- problem constants ----------------
#define B_    32
#define E_    256
#define N_    512
#define HID   64
#define H_    4
#define F_    64
#define C_    256
#define S_    255
#define BH_   (B_*H_)
#define NE_ELEMS (B_*N_*C_)
#define ADJ_ELEMS (B_*14*N_*N_)
#define MROWS ((B_*N_)/128)

#define PA 20
#define PW 136
#define FQ 8
#define PV 9

// fill work distribution (units of 256-thread fill blocks; total 14336)
#define FB_FEAT  0
#define NU_FEAT  512
#define FB_G64   (FB_FEAT + NU_FEAT)        // 512
#define NU_G64   1024
#define FB_SS1   (FB_G64 + NU_G64)          // 1536
#define NU_SS    1024
#define FB_FS1   (FB_SS1 + NU_SS)           // 2560
#define NU_FS    3584
#define FB_G256  (FB_FS1 + NU_FS)           // 6144
#define NU_G256  3584
#define FB_SS2   (FB_G256 + NU_G256)        // 9728
#define FB_FS2   (FB_SS2 + NU_SS)           // 10752
// end = 14336

// ---------------- scratch ----------------
__device__ float  g_x  [B_*N_*HID];
__device__ float  g_h  [B_*N_*C_];
__device__ float  g_o1 [B_*N_*C_];
__device__ int    g_sidx[BH_*N_];
__device__ float  g_e1 [BH_*N_];
__device__ float  g_e2 [BH_*N_];
__device__ int    g_t  [BH_*N_];
__device__ float  g_c1 [BH_*N_];
__device__ float  g_c2 [BH_*N_];
__device__ float  g_ns [BH_*N_];

__device__ __forceinline__ float to_tf32(float x) {
    float r; asm("cvt.rna.tf32.f32 %0, %1;" : "=f"(r) : "f"(x)); return r;
}

__device__ __forceinline__ void mma_tf32(float4& d,
                                         uint32_t a0, uint32_t a1, uint32_t a2, uint32_t a3,
                                         uint32_t b0, uint32_t b1) {
    asm("mma.sync.aligned.m16n8k8.row.col.f32.tf32.tf32.f32 "
        "{%0,%1,%2,%3},{%4,%5,%6,%7},{%8,%9},{%0,%1,%2,%3};"
        : "+f"(d.x), "+f"(d.y), "+f"(d.z), "+f"(d.w)
        : "r"(a0), "r"(a1), "r"(a2), "r"(a3), "r"(b0), "r"(b1));
}

// ============================================================
// Adjacency fill unit: 256 virtual threads, 32 elements each.
// fid in [0, 14336): 16 rows of one (b, r) slice.
// ============================================================
__device__ __forceinline__ void fill_unit(int fid, int t, float* __restrict__ out) {
    int x = fid & 31;
    int rest = fid >> 5;
    int r = rest % 14;
    int b = rest / 14;
    int n  = x * 16 + (t >> 4);
    int m0 = (t & 15) * 32;
    float* p = out + ((((long long)b * 14 + r) * N_ + n) << 9) + m0;
    float4* p4 = reinterpret_cast<float4*>(p);

    if (r < 13) {
        float4 z = make_float4(0.f, 0.f, 0.f, 0.f);
        #pragma unroll
        for (int q = 0; q < 8; q++) __stcs(p4 + q, z);
        if (r >= 11) {
            int cu = n + 2;
            if (cu < N_ && cu >= m0 && cu < m0 + 32) {
                int rel = ((n & 3) == 0 || (n & 3) == 3) ? 11 : 12;
                if (rel == r) p[cu - m0] = 1.f;
            }
            int cd = n - 2;
            if (cd >= 0 && cd >= m0 && cd < m0 + 32) {
                int pp = n - 2;
                int rel = ((pp & 3) == 0 || (pp & 3) == 3) ? 11 : 12;
                if (rel == r) p[cd - m0] = 1.f;
            }
        }
        return;
    }
    if (n + 3 < m0 || n - 3 >= m0 + 32) {
        float4 o1 = make_float4(1.f, 1.f, 1.f, 1.f);
        #pragma unroll
        for (int q = 0; q < 8; q++) __stcs(p4 + q, o1);
        return;
    }
    int sp1 = -1, sp2 = -1;
    int nm = n & 3;
    if (nm == 0) {
        if (n <= 508) sp1 = n + 3;
        if (n >= 4)   sp2 = n - 1;
    } else if (nm == 3) {
        if (n <= 507) sp1 = n + 1;
        sp2 = n - 3;
    }
    float vals[32];
    #pragma unroll
    for (int q = 0; q < 32; q++) {
        int m = m0 + q;
        bool zero = (m == n) | (m == n - 2) | (m == n + 2) | (m == sp1) | (m == sp2);
        vals[q] = zero ? 0.f : 1.f;
    }
    #pragma unroll
    for (int q = 0; q < 8; q++)
        __stcs(p4 + q, make_float4(vals[4*q], vals[4*q+1], vals[4*q+2], vals[4*q+3]));
}

__global__ void scatter_kernel(const int* __restrict__ shot, float* __restrict__ out) {
    int idx = blockIdx.x * 256 + threadIdx.x;
    if (idx >= B_ * S_) return;
    int b = idx / S_, s = idx % S_;
    int r = shot[idx];
    int i, j;
    if ((s & 1) == 0) { i = 2 * s;     j = 2 * s + 3; }
    else              { i = 2 * s + 1; j = 2 * s + 2; }
    long long base = ((long long)b * 14 + r) * (N_ * N_);
    out[base + (long long)i * N_ + j] = 1.f;
    out[base + (long long)j * N_ + i] = 1.f;
}

// ============================================================
// Kernel 2: node features (+ fill tail blocks).
// ============================================================
__global__ void feat_kernel(const int* __restrict__ player,
                            const float* __restrict__ Ax, const float* __restrict__ Ay,
                            const float* __restrict__ Bx, const float* __restrict__ By,
                            const float* __restrict__ emb,
                            const float* __restrict__ Wc, const float* __restrict__ bc,
                            const float* __restrict__ Wm, const float* __restrict__ bm,
                            float* __restrict__ x, float* __restrict__ adj, int do_fill) {
    int blk = blockIdx.x;
    if (blk >= B_ * 16) {
        if (do_fill) fill_unit(FB_FEAT + blk - B_ * 16, threadIdx.x, adj);
        return;
    }
    __shared__ float feat[32][64];
    __shared__ float wms[64 * 64];
    int b = blk >> 4;
    int n0 = (blk & 15) * 32;
    int tid = threadIdx.x;

    #pragma unroll
    for (int it = 0; it < 16; it++) wms[it * 256 + tid] = Wm[it * 256 + tid];

    #pragma unroll
    for (int it = 0; it < 8; it++) {
        int o = it * 256 + tid;
        int nl = o >> 6, c = o & 63;
        int n = n0 + nl;
        int e = n >> 1;
        float val;
        if (c < 32) {
            float cx, cy;
            if ((n & 1) == 0) { cx = Ax[b * E_ + e]; cy = Ay[b * E_ + e]; }
            else              { cx = Bx[b * E_ + e]; cy = By[b * E_ + e]; }
            val = fmaxf(cx * Wc[c] + cy * Wc[32 + c] + bc[c], 0.f);
        } else {
            int pid = player[b * 2 + (n & 1)];
            val = emb[pid * 32 + (c - 32)];
        }
        feat[nl][c] = val;
    }
    __syncthreads();

    #pragma unroll
    for (int it = 0; it < 8; it++) {
        int o = it * 256 + tid;
        int nl = o >> 6, k = o & 63;
        float acc = bm[k];
        #pragma unroll
        for (int c = 0; c < 64; c++) acc += feat[nl][c] * wms[c * 64 + k];
        x[(b * N_ + n0 + nl) * HID + k] = acc;
    }
}

// ============================================================
// Kernel 3: tf32-MMA SGEMM (+ fill tail blocks).
// ============================================================
template<int KIN>
__global__ void __launch_bounds__(256, 2)
gemm_kernel(const float* __restrict__ A, const float* __restrict__ W,
            float* __restrict__ C, float* __restrict__ adj, int fill_base, int do_fill) {
    if (blockIdx.y >= MROWS) {
        if (do_fill) fill_unit(fill_base + (blockIdx.y - MROWS) * 2 + blockIdx.x, threadIdx.x, adj);
        return;
    }
    __shared__ float As[2][128 * PA];
    __shared__ float Ws[2][16 * PW];
    const int Kout = C_;
    int tid = threadIdx.x;
    int mt = blockIdx.y * 128, nt = blockIdx.x * 128;
    int wid = tid >> 5, lane = tid & 31;
    int g = lane >> 2, t4 = lane & 3;
    int m0w = (wid >> 1) * 32;
    int n0w = (wid & 1) * 64;

    int ar = tid >> 1;
    int ak = (tid & 1) * 8;
    int wr = tid >> 4;
    int wc = (tid & 15) * 8;

    float4 acc[2][8];
    #pragma unroll
    for (int mi = 0; mi < 2; mi++)
        #pragma unroll
        for (int ni = 0; ni < 8; ni++) acc[mi][ni] = make_float4(0.f, 0.f, 0.f, 0.f);

    const float* Arow = &A[(long long)(mt + ar) * KIN];

    {
        float4 a0 = *reinterpret_cast<const float4*>(&Arow[ak]);
        float4 a1 = *reinterpret_cast<const float4*>(&Arow[ak + 4]);
        float* d = &As[0][ar * PA + ak];
        d[0] = to_tf32(a0.x); d[1] = to_tf32(a0.y); d[2] = to_tf32(a0.z); d[3] = to_tf32(a0.w);
        d[4] = to_tf32(a1.x); d[5] = to_tf32(a1.y); d[6] = to_tf32(a1.z); d[7] = to_tf32(a1.w);
        float4 w0 = *reinterpret_cast<const float4*>(&W[(long long)wr * Kout + nt + wc]);
        float4 w1 = *reinterpret_cast<const float4*>(&W[(long long)wr * Kout + nt + wc + 4]);
        float* e = &Ws[0][wr * PW + wc];
        e[0] = to_tf32(w0.x); e[1] = to_tf32(w0.y); e[2] = to_tf32(w0.z); e[3] = to_tf32(w0.w);
        e[4] = to_tf32(w1.x); e[5] = to_tf32(w1.y); e[6] = to_tf32(w1.z); e[7] = to_tf32(w1.w);
    }
    __syncthreads();

    int buf = 0;
    for (int kt = 0; kt < KIN; kt += 16) {
        bool notlast = (kt + 16 < KIN);
        float4 na0, na1, nw0, nw1;
        if (notlast) {
            na0 = *reinterpret_cast<const float4*>(&Arow[kt + 16 + ak]);
            na1 = *reinterpret_cast<const float4*>(&Arow[kt + 16 + ak + 4]);
            nw0 = *reinterpret_cast<const float4*>(&W[(long long)(kt + 16 + wr) * Kout + nt + wc]);
            nw1 = *reinterpret_cast<const float4*>(&W[(long long)(kt + 16 + wr) * Kout + nt + wc + 4]);
        }
        const float* Ab = As[buf];
        const float* Wb = Ws[buf];
        #pragma unroll
        for (int ks = 0; ks < 16; ks += 8) {
            uint32_t af[2][4];
            #pragma unroll
            for (int mi = 0; mi < 2; mi++) {
                int r0 = m0w + mi * 16 + g;
                af[mi][0] = __float_as_uint(Ab[(r0    ) * PA + ks + t4    ]);
                af[mi][1] = __float_as_uint(Ab[(r0 + 8) * PA + ks + t4    ]);
                af[mi][2] = __float_as_uint(Ab[(r0    ) * PA + ks + t4 + 4]);
                af[mi][3] = __float_as_uint(Ab[(r0 + 8) * PA + ks + t4 + 4]);
            }
            uint32_t bf[8][2];
            #pragma unroll
            for (int ni = 0; ni < 8; ni++) {
                int c0 = n0w + ni * 8 + g;
                bf[ni][0] = __float_as_uint(Wb[(ks + t4    ) * PW + c0]);
                bf[ni][1] = __float_as_uint(Wb[(ks + t4 + 4) * PW + c0]);
            }
            #pragma unroll
            for (int mi = 0; mi < 2; mi++)
                #pragma unroll
                for (int ni = 0; ni < 8; ni++)
                    mma_tf32(acc[mi][ni], af[mi][0], af[mi][1], af[mi][2], af[mi][3],
                             bf[ni][0], bf[ni][1]);
        }
        if (notlast) {
            int nb = buf ^ 1;
            float* d = &As[nb][ar * PA + ak];
            d[0] = to_tf32(na0.x); d[1] = to_tf32(na0.y); d[2] = to_tf32(na0.z); d[3] = to_tf32(na0.w);
            d[4] = to_tf32(na1.x); d[5] = to_tf32(na1.y); d[6] = to_tf32(na1.z); d[7] = to_tf32(na1.w);
            float* e = &Ws[nb][wr * PW + wc];
            e[0] = to_tf32(nw0.x); e[1] = to_tf32(nw0.y); e[2] = to_tf32(nw0.z); e[3] = to_tf32(nw0.w);
            e[4] = to_tf32(nw1.x); e[5] = to_tf32(nw1.y); e[6] = to_tf32(nw1.z); e[7] = to_tf32(nw1.w);
            __syncthreads();
        }
        buf ^= 1;
    }

    #pragma unroll
    for (int mi = 0; mi < 2; mi++) {
        #pragma unroll
        for (int ni = 0; ni < 8; ni++) {
            int row = mt + m0w + mi * 16 + g;
            int col = nt + n0w + ni * 8 + 2 * t4;
            float4 v = acc[mi][ni];
            *reinterpret_cast<float2*>(&C[(long long)row * Kout + col]) = make_float2(v.x, v.y);
            *reinterpret_cast<float2*>(&C[(long long)(row + 8) * Kout + col]) = make_float2(v.z, v.w);
        }
    }
}

// ============================================================
// Kernel 5a: fused score + bitonic sort + scalar scans + coeffs
// (+ fill tail blocks: 512 threads = 2 fill units).
// ============================================================
__global__ void sortscan_kernel(const float* __restrict__ h, const float* __restrict__ att,
                                int* __restrict__ sidx_g, float* __restrict__ e1_g,
                                float* __restrict__ e2_g, int* __restrict__ t_g,
                                float* __restrict__ c1_g, float* __restrict__ c2_g,
                                float* __restrict__ ns_g,
                                float* __restrict__ adj, int fill_base, int do_fill) {
    int bh = blockIdx.x;
    if (bh >= BH_) {
        if (do_fill)
            fill_unit(fill_base + (bh - BH_) * 2 + (threadIdx.x >> 8), threadIdx.x & 255, adj);
        return;
    }
    int b = bh >> 2, hd = bh & 3;
    int i = threadIdx.x;
    __shared__ float satt[128];
    __shared__ float sv[N_];
    __shared__ int   si[N_];
    __shared__ float sP1[N_ + 1], sP2[N_ + 1];
    __shared__ float sbuf[N_];

    if (i < 128) satt[i] = att[hd * 128 + i];
    __syncthreads();

    const float4* hrow = reinterpret_cast<const float4*>(&h[((long long)(b * N_ + i)) * C_ + hd * 64]);
    float a = 0.f, bval = 0.f;
    #pragma unroll
    for (int q = 0; q < 16; q++) {
        float4 v = hrow[q];
        float4 w1 = *reinterpret_cast<const float4*>(&satt[q * 4]);
        float4 w2 = *reinterpret_cast<const float4*>(&satt[64 + q * 4]);
        a    += v.x * w1.x + v.y * w1.y + v.z * w1.z + v.w * w1.w;
        bval += v.x * w2.x + v.y * w2.y + v.z * w2.z + v.w * w2.w;
    }

    sbuf[i] = bval; __syncthreads();
    #pragma unroll
    for (int o = 256; o > 0; o >>= 1) {
        if (i < o) sbuf[i] = fmaxf(sbuf[i], sbuf[i + o]);
        __syncthreads();
    }
    float mb = sbuf[0];
    __syncthreads();

    sv[i] = bval - mb; si[i] = i;
    __syncthreads();
    for (int k = 2; k <= N_; k <<= 1) {
        for (int j = k >> 1; j > 0; j >>= 1) {
            int l = i ^ j;
            if (l > i) {
                bool up = ((i & k) == 0);
                float v0 = sv[i], v1 = sv[l];
                if ((v0 > v1) == up) {
                    sv[i] = v1; sv[l] = v0;
                    int t0 = si[i]; si[i] = si[l]; si[l] = t0;
                }
            }
            __syncthreads();
        }
    }

    float e1 = __expf(sv[i]);
    float e2 = __expf(0.2f * sv[i]);

    sbuf[i] = e2; __syncthreads();
    for (int o = 1; o < N_; o <<= 1) {
        float v = sbuf[i];
        if (i >= o) v += sbuf[i - o];
        __syncthreads();
        sbuf[i] = v;
        __syncthreads();
    }
    sP2[i + 1] = sbuf[i];
    if (i == 0) sP2[0] = 0.f;
    __syncthreads();
    sbuf[i] = e1; __syncthreads();
    for (int o = 1; o < N_; o <<= 1) {
        float v = sbuf[i];
        if (i + o < N_) v += sbuf[i + o];
        __syncthreads();
        sbuf[i] = v;
        __syncthreads();
    }
    sP1[i] = sbuf[i];
    if (i == 0) sP1[N_] = 0.f;
    __syncthreads();

    sidx_g[bh * N_ + i] = si[i];
    e1_g[bh * N_ + i] = e1;
    e2_g[bh * N_ + i] = e2;

    float thr = -a - mb;
    int lo = 0, hi = N_;
    while (lo < hi) {
        int mid = (lo + hi) >> 1;
        if (sv[mid] > thr) hi = mid; else lo = mid + 1;
    }
    int t = lo;
    float s = a + mb;
    float m = s > 0.f ? s : 0.2f * s;
    float c1v = __expf(s - m);
    float c2v = __expf(0.2f * s - m);
    float sci = a + bval;
    float lsci = sci > 0.f ? sci : 0.2f * sci;
    float ns = __expf(lsci - m);
    float Z = c1v * sP1[t] + c2v * sP2[t] - ns;
    float rz = 1.f / fmaxf(Z, 1e-35f);
    t_g [bh * N_ + i] = t;
    c1_g[bh * N_ + i] = c1v * rz;
    c2_g[bh * N_ + i] = c2v * rz;
    ns_g[bh * N_ + i] = ns * rz;
}

// ============================================================
// Kernel 5b: FUSED vector scans + emit (+ fill tail blocks).
// ============================================================
__global__ void __launch_bounds__(512, 2)
fusedscan_kernel(const float* __restrict__ h,
                 const int* __restrict__ sidx_g,
                 const float* __restrict__ e1_g, const float* __restrict__ e2_g,
                 const int* __restrict__ t_g, const float* __restrict__ c1_g,
                 const float* __restrict__ c2_g, const float* __restrict__ ns_g,
                 float* __restrict__ out, int dorelu,
                 float* __restrict__ adj, int fill_base, int do_fill) {
    int bh = blockIdx.x;
    if (bh >= BH_) {
        if (do_fill) {
            int fid = fill_base + ((bh - BH_) * 8 + blockIdx.y) * 2 + (threadIdx.x >> 8);
            fill_unit(fid, threadIdx.x & 255, adj);
        }
        return;
    }
    __shared__ float V1h[N_ + 1][PV];
    __shared__ float V2h[N_ + 1][PV];
    __shared__ float tot1[16][FQ], tot2[16][FQ];
    __shared__ float suf1[17][FQ], pre2[17][FQ];
    __shared__ int   sIdx[N_];
    __shared__ int   sT[N_];
    __shared__ float sC1[N_], sC2[N_], sNS[N_];

    int fo = blockIdx.y * FQ;
    int b = bh >> 2, hd = bh & 3;
    int tid = threadIdx.x;
    int w = tid >> 5, l = tid & 31;

    int myIdx = sidx_g[bh * N_ + tid];
    sIdx[tid] = myIdx;
    sT[tid]   = t_g [bh * N_ + tid];
    sC1[tid]  = c1_g[bh * N_ + tid];
    sC2[tid]  = c2_g[bh * N_ + tid];
    sNS[tid]  = ns_g[bh * N_ + tid];
    float ev1 = e1_g[bh * N_ + tid];
    float ev2 = e2_g[bh * N_ + tid];
    if (tid < FQ) { V1h[N_][tid] = 0.f; V2h[N_][tid] = 0.f; }

    const float* hb = h + (long long)b * N_ * C_ + hd * 64 + fo;
    float hv[FQ];
    {
        float4 v0 = *reinterpret_cast<const float4*>(&hb[(long long)myIdx * C_]);
        float4 v1 = *reinterpret_cast<const float4*>(&hb[(long long)myIdx * C_ + 4]);
        hv[0] = v0.x; hv[1] = v0.y; hv[2] = v0.z; hv[3] = v0.w;
        hv[4] = v1.x; hv[5] = v1.y; hv[6] = v1.z; hv[7] = v1.w;
    }

    float p1[FQ], p2[FQ];
    #pragma unroll
    for (int f = 0; f < FQ; f++) { p1[f] = ev1 * hv[f]; p2[f] = ev2 * hv[f]; }
    #pragma unroll
    for (int off = 1; off < 32; off <<= 1) {
        #pragma unroll
        for (int f = 0; f < FQ; f++) {
            float nu = __shfl_up_sync(0xffffffffu, p2[f], off);
            float nd = __shfl_down_sync(0xffffffffu, p1[f], off);
            if (l >= off)     p2[f] += nu;
            if (l + off < 32) p1[f] += nd;
        }
    }
    #pragma unroll
    for (int f = 0; f < FQ; f++) {
        V2h[tid][f] = p2[f] - ev2 * hv[f];
        V1h[tid][f] = p1[f];
    }
    if (l == 31) {
        #pragma unroll
        for (int f = 0; f < FQ; f++) tot2[w][f] = p2[f];
    }
    if (l == 0) {
        #pragma unroll
        for (int f = 0; f < FQ; f++) tot1[w][f] = p1[f];
    }
    __syncthreads();

    if (tid < FQ) {
        int f = tid;
        float pre = 0.f;
        #pragma unroll
        for (int c = 0; c < 16; c++) { pre2[c][f] = pre; pre += tot2[c][f]; }
        pre2[16][f] = pre;
    } else if (tid < 2 * FQ) {
        int f = tid - FQ;
        float s = 0.f;
        suf1[16][f] = 0.f;
        #pragma unroll
        for (int c = 15; c >= 0; c--) { suf1[c][f] = s; s += tot1[c][f]; }
    }
    __syncthreads();

    {
        int i = myIdx;
        int t = sT[i];
        float c1 = sC1[i], c2 = sC2[i], ns = sNS[i];
        int tc = t >> 5;
        float o[FQ];
        #pragma unroll
        for (int f = 0; f < FQ; f++) {
            float v1 = V1h[t][f] + suf1[tc][f];
            float v2 = V2h[t][f] + pre2[tc][f];
            float val = c1 * v1 + c2 * v2 - ns * hv[f];
            o[f] = dorelu ? fmaxf(val, 0.f) : val;
        }
        float* outp = out + ((long long)(b * N_ + i)) * C_ + hd * 64 + fo;
        *reinterpret_cast<float4*>(outp)     = make_float4(o[0], o[1], o[2], o[3]);
        *reinterpret_cast<float4*>(outp + 4) = make_float4(o[4], o[5], o[6], o[7]);
    }
}

// ============================================================
// launch — fill units distributed across ALL chain kernels so the
// DRAM-bound adjacency writes overlap the compute/latency-bound chain.
// ============================================================
extern "C" void kernel_launch(void* const* d_in, const int* in_sizes, int n_in,
                              void* d_out, int out_size) {
    int off = (n_in >= 16) ? 1 : 0;
    const int*   player = (const int*)  d_in[0];
    const int*   shot   = (const int*)  d_in[1];
    const float* Ax     = (const float*)d_in[2];
    const float* Ay     = (const float*)d_in[3];
    const float* Bx     = (const float*)d_in[4];
    const float* By     = (const float*)d_in[5];
    const float* emb    = (const float*)d_in[6 + off];
    const float* Wc     = (const float*)d_in[7 + off];
    const float* bc     = (const float*)d_in[8 + off];
    const float* Wm     = (const float*)d_in[9 + off];
    const float* bm     = (const float*)d_in[10 + off];
    const float* lin1   = (const float*)d_in[11 + off];
    const float* att1   = (const float*)d_in[12 + off];
    const float* lin2   = (const float*)d_in[13 + off];
    const float* att2   = (const float*)d_in[14 + off];

    float* out_ne  = (float*)d_out;
    float* out_adj = out_ne + NE_ELEMS;

    float *px, *ph, *po1;
    float *pe1, *pe2, *pc1, *pc2, *pns;
    int *psidx, *pt;
    cudaGetSymbolAddress((void**)&px,  g_x);
    cudaGetSymbolAddress((void**)&ph,  g_h);
    cudaGetSymbolAddress((void**)&po1, g_o1);
    cudaGetSymbolAddress((void**)&psidx, g_sidx);
    cudaGetSymbolAddress((void**)&pe1, g_e1);
    cudaGetSymbolAddress((void**)&pe2, g_e2);
    cudaGetSymbolAddress((void**)&pt,  g_t);
    cudaGetSymbolAddress((void**)&pc1, g_c1);
    cudaGetSymbolAddress((void**)&pc2, g_c2);
    cudaGetSymbolAddress((void**)&pns, g_ns);

    int fa = (out_size >= NE_ELEMS + ADJ_ELEMS) ? 1 : 0;

    dim3 featg(B_ * 16 + (fa ? NU_FEAT : 0));
    dim3 g64g (2, MROWS + (fa ? NU_G64  / 2 : 0));
    dim3 g256g(2, MROWS + (fa ? NU_G256 / 2 : 0));
    dim3 ssg  (BH_ + (fa ? NU_SS / 2 : 0));
    dim3 fsg  (BH_ + (fa ? NU_FS / 16 : 0), F_ / FQ);

    feat_kernel<<<featg, 256>>>(player, Ax, Ay, Bx, By, emb, Wc, bc, Wm, bm, px, out_adj, fa);

    // ---- layer 1 ----
    gemm_kernel<HID><<<g64g, 256>>>(px, lin1, ph, out_adj, FB_G64, fa);
    sortscan_kernel<<<ssg, N_>>>(ph, att1, psidx, pe1, pe2, pt, pc1, pc2, pns, out_adj, FB_SS1, fa);
    fusedscan_kernel<<<fsg, 512>>>(ph, psidx, pe1, pe2, pt, pc1, pc2, pns, po1, 1, out_adj, FB_FS1, fa);

    // ---- layer 2 ----
    gemm_kernel<C_><<<g256g, 256>>>(po1, lin2, ph, out_adj, FB_G256, fa);
    sortscan_kernel<<<ssg, N_>>>(ph, att2, psidx, pe1, pe2, pt, pc1, pc2, pns, out_adj, FB_SS2, fa);
    fusedscan_kernel<<<fsg, 512>>>(ph, psidx, pe1, pe2, pt, pc1, pc2, pns, out_ne, 0, out_adj, FB_FS2, fa);

    if (fa) scatter_kernel<<<(B_ * S_ + 255) / 256, 256>>>(shot, out_adj);
}